// round 14
// baseline (speedup 1.0000x reference)
#include <cuda_runtime.h>
#include <cuda_bf16.h>
#include <cuda_fp8.h>
#include <math.h>
#include <stdint.h>

#define ENT   52
#define INNER 64
#define BB    8
#define SS    512
#define HH    768
#define NOUT  6656    /* ENT*2*INNER */
#define KDIM  1536
#define MDIM  4096    /* BB*SS */
#define BIGF  1000000000000.0f
#define BLKB  16384   /* one 16KB swizzled block */
#define WSCALE 32.0f
#define WISCALE (1.0f / 32.0f)

// ---------------- scratch (device globals; no allocations allowed) ----------
__device__ float g_cls_emb[BB * HH];
__device__ __align__(16) uint8_t g_hidden_blk[(size_t)32 * 6 * BLKB];         // 3.1 MB
__device__ __align__(16) uint8_t g_wbf_blk[(size_t)ENT * 6 * BLKB];           // 5.1 MB
__device__ float2 g_rope[SS * 32];

// ---------------- PTX helpers ----------------------------------------------
__device__ __forceinline__ uint32_t smem_u32(const void* p) {
    uint32_t a;
    asm("{ .reg .u64 t; cvta.to.shared.u64 t, %1; cvt.u32.u64 %0, t; }" : "=r"(a) : "l"(p));
    return a;
}
__device__ __forceinline__ void mbar_init(uint32_t a, uint32_t n) {
    asm volatile("mbarrier.init.shared.b64 [%0], %1;" :: "r"(a), "r"(n) : "memory");
}
__device__ __forceinline__ void mbar_expect(uint32_t a, uint32_t tx) {
    asm volatile("mbarrier.arrive.expect_tx.shared.b64 _, [%0], %1;" :: "r"(a), "r"(tx) : "memory");
}
__device__ __forceinline__ void mbar_wait(uint32_t a, uint32_t ph) {
    asm volatile("{\n\t.reg .pred P;\n\t"
                 "LW_%=:\n\t"
                 "mbarrier.try_wait.parity.shared.b64 P, [%0], %1;\n\t"
                 "@!P bra LW_%=;\n\t}"
                 :: "r"(a), "r"(ph) : "memory");
}
__device__ __forceinline__ void bulk_cp(uint32_t dst, const void* src, uint32_t bytes,
                                        uint32_t mbar) {
    asm volatile("cp.async.bulk.shared::cta.global.mbarrier::complete_tx::bytes "
                 "[%0], [%1], %2, [%3];"
                 :: "r"(dst), "l"(src), "r"(bytes), "r"(mbar) : "memory");
}
__device__ __forceinline__ void ldsm4(uint32_t* r, uint32_t addr) {
    asm volatile("ldmatrix.sync.aligned.m8n8.x4.shared.b16 {%0,%1,%2,%3}, [%4];"
                 : "=r"(r[0]), "=r"(r[1]), "=r"(r[2]), "=r"(r[3]) : "r"(addr));
}
__device__ __forceinline__ void mma16816(float* c, const uint32_t* a, const uint32_t* b) {
    asm volatile(
        "mma.sync.aligned.m16n8k16.row.col.f32.bf16.bf16.f32 "
        "{%0,%1,%2,%3}, {%4,%5,%6,%7}, {%8,%9}, {%0,%1,%2,%3};"
        : "+f"(c[0]), "+f"(c[1]), "+f"(c[2]), "+f"(c[3])
        : "r"(a[0]), "r"(a[1]), "r"(a[2]), "r"(a[3]), "r"(b[0]), "r"(b[1]));
}
__device__ __forceinline__ void mma16832f8(float* c, const uint32_t* a, const uint32_t* b) {
    asm volatile(
        "mma.sync.aligned.m16n8k32.row.col.f32.e4m3.e4m3.f32 "
        "{%0,%1,%2,%3}, {%4,%5,%6,%7}, {%8,%9}, {%0,%1,%2,%3};"
        : "+f"(c[0]), "+f"(c[1]), "+f"(c[2]), "+f"(c[3])
        : "r"(a[0]), "r"(a[1]), "r"(a[2]), "r"(a[3]), "r"(b[0]), "r"(b[1]));
}
__device__ __forceinline__ uint32_t dswz(int row, int colb) {
    return (uint32_t)(row * 128 + (colb ^ ((row & 7) << 4)));
}
__device__ __forceinline__ uint32_t fp8x4(float a, float b, float c, float d) {
    __nv_fp8x2_storage_t lo = __nv_cvt_float2_to_fp8x2(make_float2(a, b),
                                                       __NV_SATFINITE, __NV_E4M3);
    __nv_fp8x2_storage_t hi = __nv_cvt_float2_to_fp8x2(make_float2(c, d),
                                                       __NV_SATFINITE, __NV_E4M3);
    return (uint32_t)lo | ((uint32_t)hi << 16);
}

// ---------------------------------------------------------------------------
// Kernel 1 (fused prep): [0,96) GRU | [96,160) rope | [160,2656) skip tiles |
//   [2656,3904) W1->fp8 (MLP4) | [3904,4672) lhs->fp8 (MLP4)
// ---------------------------------------------------------------------------
#define GRUB2 96
#define ROPEB 64
#define SKIPB 2496
#define CONVB2 (NOUT * HH / 16 / 256)   /* 1248 */
#define BHB2   (MDIM * HH / 16 / 256)   /* 768  */
#define PREPB (GRUB2 + ROPEB + SKIPB + CONVB2 + BHB2)

__global__ __launch_bounds__(256) void prep_kernel(
    const float* __restrict__ dw, const float* __restrict__ lhs,
    const float* __restrict__ cls, const float* __restrict__ h0,
    const float* __restrict__ w_ih_f, const float* __restrict__ w_hh_f,
    const float* __restrict__ b_ih_f, const float* __restrict__ b_hh_f,
    const float* __restrict__ w_ih_b, const float* __restrict__ w_hh_b,
    const float* __restrict__ b_ih_b, const float* __restrict__ b_hh_b,
    const float* __restrict__ mask, float* __restrict__ out)
{
    const int bid = blockIdx.x;
    const int tid = threadIdx.x;

    if (bid < GRUB2) {
        const int dir = bid / 48;
        const int u   = (bid % 48) * 8 + (tid >> 5);
        const int rest = tid & 31;
        const int b  = rest >> 2;
        const int ks = rest & 3;

        const float* w_ih = dir ? w_ih_b : w_ih_f;
        const float* w_hh = dir ? w_hh_b : w_hh_f;
        const float* b_ih = dir ? b_ih_b : b_ih_f;
        const float* b_hh = dir ? b_hh_b : b_hh_f;

        const float* xv = cls + b * HH;
        const float* hv = h0 + ((size_t)dir * BB + b) * 384;

        float gi[3], gh[3];
#pragma unroll
        for (int g = 0; g < 3; g++) {
            const float* w = w_ih + (size_t)(g * 384 + u) * HH + ks * 192;
            const float* x = xv + ks * 192;
            float acc = 0.0f;
#pragma unroll 8
            for (int k = 0; k < 192; k += 4) {
                float4 wq = *(const float4*)(w + k);
                float4 xq = *(const float4*)(x + k);
                acc += wq.x * xq.x + wq.y * xq.y + wq.z * xq.z + wq.w * xq.w;
            }
            gi[g] = acc;
            const float* w2 = w_hh + (size_t)(g * 384 + u) * 384 + ks * 96;
            const float* h2 = hv + ks * 96;
            float acc2 = 0.0f;
#pragma unroll 8
            for (int k = 0; k < 96; k += 4) {
                float4 wq = *(const float4*)(w2 + k);
                float4 hq = *(const float4*)(h2 + k);
                acc2 += wq.x * hq.x + wq.y * hq.y + wq.z * hq.z + wq.w * hq.w;
            }
            gh[g] = acc2;
        }
#pragma unroll
        for (int g = 0; g < 3; g++) {
            gi[g] += __shfl_xor_sync(0xFFFFFFFF, gi[g], 1);
            gi[g] += __shfl_xor_sync(0xFFFFFFFF, gi[g], 2);
            gh[g] += __shfl_xor_sync(0xFFFFFFFF, gh[g], 1);
            gh[g] += __shfl_xor_sync(0xFFFFFFFF, gh[g], 2);
        }
        if (ks == 0) {
            float i0 = gi[0] + b_ih[u],        h0v = gh[0] + b_hh[u];
            float i1 = gi[1] + b_ih[384 + u],  h1v = gh[1] + b_hh[384 + u];
            float i2 = gi[2] + b_ih[768 + u],  h2v = gh[2] + b_hh[768 + u];
            float r = 1.0f / (1.0f + expf(-(i0 + h0v)));
            float z = 1.0f / (1.0f + expf(-(i1 + h1v)));
            float n = tanhf(i2 + r * h2v);
            float hp = hv[u];
            g_cls_emb[b * HH + dir * 384 + u] = (1.0f - z) * n + z * hp;
        }
        return;
    }
    if (bid < GRUB2 + ROPEB) {
        int idx = (bid - GRUB2) * 256 + tid;
        int s = idx >> 5, t = idx & 31;
        float invf = powf(10000.0f, -2.0f * (float)t / 64.0f);
        float sn, cs;
        sincosf((float)s * invf, &sn, &cs);
        g_rope[idx] = make_float2(cs, sn);
        return;
    }
    if (bid < GRUB2 + ROPEB + SKIPB) {
        const int MTs[6] = {1, 2, 2, 3, 3, 3};
        const int NTs[6] = {0, 0, 1, 0, 1, 2};
        int idx = bid - (GRUB2 + ROPEB);
        int ti = idx % 6;
        int be = idx / 6;
        int b = be / ENT, e = be % ENT;
        int m0 = MTs[ti] * 128, n0 = NTs[ti] * 128;
        size_t rowbase = ((size_t)(b * ENT + e)) * SS;
        int cg = (tid & 31) * 4;
        float p0 = mask[b * SS + n0 + cg];
        float p1 = mask[b * SS + n0 + cg + 1];
        float p2 = mask[b * SS + n0 + cg + 2];
        float p3 = mask[b * SS + n0 + cg + 3];
        float4 v = make_float4(((p0 - 1.0f) * BIGF - BIGF) * 0.125f,
                               ((p1 - 1.0f) * BIGF - BIGF) * 0.125f,
                               ((p2 - 1.0f) * BIGF - BIGF) * 0.125f,
                               ((p3 - 1.0f) * BIGF - BIGF) * 0.125f);
        for (int r = tid >> 5; r < 128; r += 8)
            __stcs((float4*)(out + (rowbase + m0 + r) * SS + n0 + cg), v);
        return;
    }
    if (bid < GRUB2 + ROPEB + SKIPB + CONVB2) {
        // ---- W1 fp32 -> fp8 (x32), 4 float4 per thread (MLP=4) ----
        int base = (bid - (GRUB2 + ROPEB + SKIPB)) * 1024 + tid;
        float4 v[4];
#pragma unroll
        for (int j = 0; j < 4; j++) {
            int i = base + j * 256;
            v[j] = *(const float4*)(dw + (size_t)(i / 192) * KDIM + (i % 192) * 4);
        }
#pragma unroll
        for (int j = 0; j < 4; j++) {
            int i = base + j * 256;
            int n = i / 192, kq = (i % 192) * 4;
            uint32_t w = fp8x4(v[j].x * WSCALE, v[j].y * WSCALE,
                               v[j].z * WSCALE, v[j].w * WSCALE);
            int e = n >> 7, row = n & 127, ch = kq >> 7, kc = kq & 127;
            size_t off = (size_t)(e * 6 + ch) * BLKB + dswz(row, kc & 0x70) + (kc & 15);
            *(uint32_t*)(g_wbf_blk + off) = w;
        }
        return;
    }
    {
        // ---- lhs fp32 -> fp8, 4 float4 per thread (MLP=4) ----
        size_t base = ((size_t)(bid - (GRUB2 + ROPEB + SKIPB + CONVB2)) * 1024 + tid) * 4;
        float4 v[4];
#pragma unroll
        for (int j = 0; j < 4; j++)
            v[j] = *(const float4*)(lhs + base + (size_t)j * 1024);
#pragma unroll
        for (int j = 0; j < 4; j++) {
            size_t i = base + (size_t)j * 1024;
            uint32_t w = fp8x4(v[j].x, v[j].y, v[j].z, v[j].w);
            int m = (int)(i / HH), k = (int)(i % HH);
            int mt = m >> 7, row = m & 127, ch = k >> 7, kc = k & 127;
            size_t off = (size_t)(mt * 6 + ch) * BLKB + dswz(row, kc & 0x70) + (kc & 15);
            *(uint32_t*)(g_hidden_blk + off) = w;
        }
    }
}

// ---------------------------------------------------------------------------
// Kernel 2 (FUSED, 512 threads = 16 warps, 4Mx4N, warp tile 32x32):
// one CTA per (e, b). Inline ext-bias (clsw absorbed, runs in TMA bubble);
// 3-stage TMA ring dense fp8 GEMM; bias+RoPE -> bf16 q/k in SMEM; logits
// tiles interleaved after each m-tile epilogue (overlap with next TMA).
// ---------------------------------------------------------------------------
#define NST2 3
#define QK_SMEM (8 * BLKB)                         /* 131072 */
#define DSMEM_FUSED (QK_SMEM + NST2 * 2 * BLKB)    /* 229376 */

__global__ __launch_bounds__(512) void fused_kernel(const float* __restrict__ mask,
                                                    float* __restrict__ out,
                                                    const float* __restrict__ dw,
                                                    const float* __restrict__ db)
{
    extern __shared__ char fsm[];
    const uint32_t sQK   = smem_u32(fsm);
    const uint32_t sStg  = sQK + QK_SMEM;
    __shared__ uint64_t mbv[NST2];
    __shared__ float bias_s[128];
    const uint32_t mb0 = smem_u32(mbv);

    const int e = blockIdx.x;
    const int b = blockIdx.y;
    const int tid = threadIdx.x;
    const int lane = tid & 31;
    const int wid  = tid >> 5;          // 0..15
    const int warpM = wid >> 2;         // 0..3 (32-row strips)
    const int warpN = wid & 3;          // 0..3 (32-col strips)
    const int g = lane >> 2, q = lane & 3;
    const size_t rowbase = ((size_t)(b * ENT + e)) * SS;

    if (tid == 0) {
#pragma unroll
        for (int s = 0; s < NST2; s++) mbar_init(mb0 + s * 8, 1);
    }
    __syncthreads();

    auto issue = [&](int k, int st) {
        int mt = k / 6, ch = k % 6;
        mbar_expect(mb0 + st * 8, 2 * BLKB);
        bulk_cp(sStg + st * 2 * BLKB,
                g_hidden_blk + ((size_t)(b * 4 + mt) * 6 + ch) * BLKB, BLKB, mb0 + st * 8);
        bulk_cp(sStg + st * 2 * BLKB + BLKB,
                g_wbf_blk + ((size_t)e * 6 + ch) * BLKB, BLKB, mb0 + st * 8);
    };
    if (tid == 0) { issue(0, 0); issue(1, 1); issue(2, 2); }

    // ---- inline ext-bias (clsw): runs inside the TMA startup bubble --------
    {
        const int nl  = tid >> 2;        // 0..127
        const int ks4 = tid & 3;         // 0..3 (192-float k segments)
        const float* w  = dw + (size_t)(e * 128 + nl) * KDIM + HH + ks4 * 192;
        const float* cv = g_cls_emb + b * HH + ks4 * 192;
        float a0 = 0.0f;
#pragma unroll 8
        for (int k2 = 0; k2 < 192; k2 += 4) {
            float4 wq = *(const float4*)(w + k2);
            float4 cq = *(const float4*)(cv + k2);
            a0 += wq.x * cq.x + wq.y * cq.y + wq.z * cq.z + wq.w * cq.w;
        }
        a0 += __shfl_xor_sync(0xFFFFFFFF, a0, 1);
        a0 += __shfl_xor_sync(0xFFFFFFFF, a0, 2);
        if (ks4 == 0) bias_s[nl] = a0 + db[e * 128 + nl];
    }

    // ---- logits tile from SMEM qk, masked streaming stores ------------------
    auto do_logits = [&](int mt, int nt) {
        const int m0 = mt * 128, n0 = nt * 128;
        const uint32_t sQ = sQK + (uint32_t)mt * BLKB;
        const uint32_t sK = sQK + (uint32_t)(4 + nt) * BLKB;

        float lac[2][4][4];
#pragma unroll
        for (int i = 0; i < 2; i++)
#pragma unroll
            for (int j = 0; j < 4; j++)
#pragma unroll
                for (int r = 0; r < 4; r++) lac[i][j][r] = 0.0f;

#pragma unroll
        for (int kstep = 0; kstep < 4; kstep++) {
            const int colb = kstep * 32 + (lane >> 4) * 16;
            uint32_t areg[2][4], breg[4][2];
#pragma unroll
            for (int mi = 0; mi < 2; mi++)
                ldsm4(areg[mi], sQ + dswz(warpM * 32 + mi * 16 + (lane & 15), colb));
#pragma unroll
            for (int jp = 0; jp < 2; jp++) {
                uint32_t t4[4];
                ldsm4(t4, sK + dswz(warpN * 32 + jp * 16 + (lane & 15), colb));
                breg[jp * 2][0]     = t4[0];
                breg[jp * 2 + 1][0] = t4[1];
                breg[jp * 2][1]     = t4[2];
                breg[jp * 2 + 1][1] = t4[3];
            }
#pragma unroll
            for (int mi = 0; mi < 2; mi++)
#pragma unroll
                for (int j = 0; j < 4; j++)
                    mma16816(lac[mi][j], areg[mi], breg[j]);
        }

        const int nbase = n0 + warpN * 32;
        float p0[4], p1[4];
#pragma unroll
        for (int j = 0; j < 4; j++) {
            int c = nbase + j * 8 + 2 * q;
            p0[j] = mask[b * SS + c];
            p1[j] = mask[b * SS + c + 1];
        }
#pragma unroll
        for (int mi = 0; mi < 2; mi++) {
#pragma unroll
            for (int h = 0; h < 2; h++) {
                int m = m0 + warpM * 32 + mi * 16 + h * 8 + g;
                size_t orow = (rowbase + m) * SS;
#pragma unroll
                for (int j = 0; j < 4; j++) {
                    int c = nbase + j * 8 + 2 * q;
                    float x = lac[mi][j][h * 2];
                    float y = lac[mi][j][h * 2 + 1];
                    x = x * p0[j] - (1.0f - p0[j]) * BIGF;
                    y = y * p1[j] - (1.0f - p1[j]) * BIGF;
                    if (m > c)     x -= BIGF;
                    if (m > c + 1) y -= BIGF;
                    __stcs((float2*)(out + orow + c), make_float2(x * 0.125f, y * 0.125f));
                }
            }
        }
    };

    float acc[2][4][4];
#pragma unroll
    for (int i = 0; i < 2; i++)
#pragma unroll
        for (int j = 0; j < 4; j++)
#pragma unroll
            for (int r = 0; r < 4; r++) acc[i][j][r] = 0.0f;

    // ---- dense phase: 24 chunks, 3-stage ring, logits interleaved ----------
    for (int k = 0; k < 24; k++) {
        const int st = k % NST2;
        mbar_wait(mb0 + st * 8, (uint32_t)((k / NST2) & 1));

        const uint32_t aS = sStg + st * 2 * BLKB;
        const uint32_t bS = aS + BLKB;
#pragma unroll
        for (int kstep = 0; kstep < 4; kstep++) {
            const int colb = kstep * 32 + (lane >> 4) * 16;
            uint32_t areg[2][4], breg[4][2];
#pragma unroll
            for (int mi = 0; mi < 2; mi++)
                ldsm4(areg[mi], aS + dswz(warpM * 32 + mi * 16 + (lane & 15), colb));
#pragma unroll
            for (int jp = 0; jp < 2; jp++) {
                uint32_t t4[4];
                ldsm4(t4, bS + dswz(warpN * 32 + jp * 16 + (lane & 15), colb));
                breg[jp * 2][0]     = t4[0];
                breg[jp * 2 + 1][0] = t4[1];
                breg[jp * 2][1]     = t4[2];
                breg[jp * 2 + 1][1] = t4[3];
            }
#pragma unroll
            for (int mi = 0; mi < 2; mi++)
#pragma unroll
                for (int j = 0; j < 4; j++)
                    mma16832f8(acc[mi][j], areg[mi], breg[j]);
        }

        const bool tile_done = ((k % 6) == 5);
        if (tile_done) {
            // ---- m-tile epilogue: unscale + bias + RoPE -> bf16 SMEM qk ----
            const int mt = k / 6;
#pragma unroll
            for (int mi = 0; mi < 2; mi++) {
#pragma unroll
                for (int h = 0; h < 2; h++) {
                    int row = warpM * 32 + mi * 16 + h * 8 + g;
                    int s = mt * 128 + row;
#pragma unroll
                    for (int j = 0; j < 4; j++) {
                        int c = warpN * 32 + j * 8 + 2 * q;
                        float x = acc[mi][j][h * 2]     * WISCALE + bias_s[c];
                        float y = acc[mi][j][h * 2 + 1] * WISCALE + bias_s[c + 1];
                        int t = (c & 63) >> 1;
                        float2 rc = g_rope[s * 32 + t];
                        float rx = x * rc.x - y * rc.y;
                        float ry = y * rc.x + x * rc.y;
                        __nv_bfloat162 p = __floats2bfloat162_rn(rx, ry);
                        int qk = c >> 6, col = c & 63;
                        uint32_t off = (uint32_t)(qk * 4 + mt) * BLKB
                                     + dswz(row, (col >> 3) << 4) + (col & 7) * 2;
                        *(uint32_t*)(fsm + off) = *(uint32_t*)&p;
                        acc[mi][j][h * 2] = 0.0f;
                        acc[mi][j][h * 2 + 1] = 0.0f;
                    }
                }
            }
        }

        __syncthreads();               // stage consumed (+ epi/bias visible)
        if (tid == 0 && k + NST2 < 24) issue(k + NST2, st);

        if (tile_done) {
            const int mt = k / 6;
            for (int mt2 = 0; mt2 <= mt; mt2++)
                do_logits(mt2, mt);    // overlaps next m-tile's TMA
        }
    }
}

// ---------------------------------------------------------------------------
extern "C" void kernel_launch(void* const* d_in, const int* in_sizes, int n_in,
                              void* d_out, int out_size)
{
    const float* lhs    = (const float*)d_in[0];
    const float* cls    = (const float*)d_in[1];
    const float* h0     = (const float*)d_in[2];
    const float* mask   = (const float*)d_in[3];
    const float* w_ih_f = (const float*)d_in[4];
    const float* w_hh_f = (const float*)d_in[5];
    const float* b_ih_f = (const float*)d_in[6];
    const float* b_hh_f = (const float*)d_in[7];
    const float* w_ih_b = (const float*)d_in[8];
    const float* w_hh_b = (const float*)d_in[9];
    const float* b_ih_b = (const float*)d_in[10];
    const float* b_hh_b = (const float*)d_in[11];
    const float* dw     = (const float*)d_in[12];
    const float* db     = (const float*)d_in[13];
    float* out = (float*)d_out;

    cudaFuncSetAttribute(fused_kernel, cudaFuncAttributeMaxDynamicSharedMemorySize,
                         DSMEM_FUSED);

    prep_kernel<<<PREPB, 256>>>(dw, lhs, cls, h0, w_ih_f, w_hh_f, b_ih_f, b_hh_f,
                                w_ih_b, w_hh_b, b_ih_b, b_hh_b, mask, out);

    fused_kernel<<<dim3(ENT, BB), 512, DSMEM_FUSED>>>(mask, out, dw, db);
}

// round 15
// speedup vs baseline: 1.3837x; 1.3837x over previous
#include <cuda_runtime.h>
#include <cuda_bf16.h>
#include <cuda_fp8.h>
#include <math.h>
#include <stdint.h>

#define ENT   52
#define INNER 64
#define BB    8
#define SS    512
#define HH    768
#define NOUT  6656    /* ENT*2*INNER */
#define KDIM  1536
#define MDIM  4096    /* BB*SS */
#define BIGF  1000000000000.0f
#define BLKB  16384   /* one 16KB swizzled block */
#define WSCALE 32.0f
#define WISCALE (1.0f / 32.0f)

// ---------------- scratch (device globals; no allocations allowed) ----------
__device__ float g_cls_emb[BB * HH];
__device__ float g_clsw[BB * NOUT];
__device__ __align__(16) uint8_t g_hidden_blk[(size_t)32 * 6 * BLKB];         // 3.1 MB
__device__ __align__(16) uint8_t g_wbf_blk[(size_t)ENT * 6 * BLKB];           // 5.1 MB
__device__ float2 g_rope[SS * 32];

// ---------------- PTX helpers ----------------------------------------------
__device__ __forceinline__ uint32_t smem_u32(const void* p) {
    uint32_t a;
    asm("{ .reg .u64 t; cvta.to.shared.u64 t, %1; cvt.u32.u64 %0, t; }" : "=r"(a) : "l"(p));
    return a;
}
__device__ __forceinline__ void mbar_init(uint32_t a, uint32_t n) {
    asm volatile("mbarrier.init.shared.b64 [%0], %1;" :: "r"(a), "r"(n) : "memory");
}
__device__ __forceinline__ void mbar_expect(uint32_t a, uint32_t tx) {
    asm volatile("mbarrier.arrive.expect_tx.shared.b64 _, [%0], %1;" :: "r"(a), "r"(tx) : "memory");
}
__device__ __forceinline__ void mbar_wait(uint32_t a, uint32_t ph) {
    asm volatile("{\n\t.reg .pred P;\n\t"
                 "LW_%=:\n\t"
                 "mbarrier.try_wait.parity.shared.b64 P, [%0], %1;\n\t"
                 "@!P bra LW_%=;\n\t}"
                 :: "r"(a), "r"(ph) : "memory");
}
__device__ __forceinline__ void bulk_cp(uint32_t dst, const void* src, uint32_t bytes,
                                        uint32_t mbar) {
    asm volatile("cp.async.bulk.shared::cta.global.mbarrier::complete_tx::bytes "
                 "[%0], [%1], %2, [%3];"
                 :: "r"(dst), "l"(src), "r"(bytes), "r"(mbar) : "memory");
}
__device__ __forceinline__ void ldsm4(uint32_t* r, uint32_t addr) {
    asm volatile("ldmatrix.sync.aligned.m8n8.x4.shared.b16 {%0,%1,%2,%3}, [%4];"
                 : "=r"(r[0]), "=r"(r[1]), "=r"(r[2]), "=r"(r[3]) : "r"(addr));
}
__device__ __forceinline__ void mma16816(float* c, const uint32_t* a, const uint32_t* b) {
    asm volatile(
        "mma.sync.aligned.m16n8k16.row.col.f32.bf16.bf16.f32 "
        "{%0,%1,%2,%3}, {%4,%5,%6,%7}, {%8,%9}, {%0,%1,%2,%3};"
        : "+f"(c[0]), "+f"(c[1]), "+f"(c[2]), "+f"(c[3])
        : "r"(a[0]), "r"(a[1]), "r"(a[2]), "r"(a[3]), "r"(b[0]), "r"(b[1]));
}
__device__ __forceinline__ void mma16832f8(float* c, const uint32_t* a, const uint32_t* b) {
    asm volatile(
        "mma.sync.aligned.m16n8k32.row.col.f32.e4m3.e4m3.f32 "
        "{%0,%1,%2,%3}, {%4,%5,%6,%7}, {%8,%9}, {%0,%1,%2,%3};"
        : "+f"(c[0]), "+f"(c[1]), "+f"(c[2]), "+f"(c[3])
        : "r"(a[0]), "r"(a[1]), "r"(a[2]), "r"(a[3]), "r"(b[0]), "r"(b[1]));
}
__device__ __forceinline__ uint32_t dswz(int row, int colb) {
    return (uint32_t)(row * 128 + (colb ^ ((row & 7) << 4)));
}
__device__ __forceinline__ uint32_t fp8x4(float a, float b, float c, float d) {
    __nv_fp8x2_storage_t lo = __nv_cvt_float2_to_fp8x2(make_float2(a, b),
                                                       __NV_SATFINITE, __NV_E4M3);
    __nv_fp8x2_storage_t hi = __nv_cvt_float2_to_fp8x2(make_float2(c, d),
                                                       __NV_SATFINITE, __NV_E4M3);
    return (uint32_t)lo | ((uint32_t)hi << 16);
}

// ---------------------------------------------------------------------------
// Kernel 1 (fused prep): [0,384) GRU (16-way ksplit) | [384,448) rope |
//   [448,10432) skip tiles (32-row bands) | [10432,11680) W1->fp8 |
//   [11680,12448) lhs->fp8
// ---------------------------------------------------------------------------
#define GRUB3 384
#define ROPEB 64
#define SKIPB 9984            /* 6 tiles x 4 bands x 416 (b,e) */
#define CONVB2 (NOUT * HH / 16 / 256)   /* 1248 */
#define BHB2   (MDIM * HH / 16 / 256)   /* 768  */
#define PREPB (GRUB3 + ROPEB + SKIPB + CONVB2 + BHB2)

__global__ __launch_bounds__(256) void prep_kernel(
    const float* __restrict__ dw, const float* __restrict__ lhs,
    const float* __restrict__ cls, const float* __restrict__ h0,
    const float* __restrict__ w_ih_f, const float* __restrict__ w_hh_f,
    const float* __restrict__ b_ih_f, const float* __restrict__ b_hh_f,
    const float* __restrict__ w_ih_b, const float* __restrict__ w_hh_b,
    const float* __restrict__ b_ih_b, const float* __restrict__ b_hh_b,
    const float* __restrict__ mask, float* __restrict__ out)
{
    const int bid = blockIdx.x;
    const int tid = threadIdx.x;

    if (bid < GRUB3) {
        // ---- GRU: 384 blocks = 192 unit-chunks x 2 dirs.
        //      256 thr = 2 units x 8 batches x 16 ksplits, shfl reduce.
        const int dir = bid / 192;
        const int u   = (bid % 192) * 2 + (tid >> 7);
        const int b   = (tid >> 4) & 7;
        const int ks  = tid & 15;

        const float* w_ih = dir ? w_ih_b : w_ih_f;
        const float* w_hh = dir ? w_hh_b : w_hh_f;
        const float* b_ih = dir ? b_ih_b : b_ih_f;
        const float* b_hh = dir ? b_hh_b : b_hh_f;

        const float* xv = cls + b * HH;
        const float* hv = h0 + ((size_t)dir * BB + b) * 384;

        float gi[3], gh[3];
#pragma unroll
        for (int g = 0; g < 3; g++) {
            const float* w = w_ih + (size_t)(g * 384 + u) * HH + ks * 48;
            const float* x = xv + ks * 48;
            float acc = 0.0f;
#pragma unroll
            for (int k = 0; k < 48; k += 4) {
                float4 wq = *(const float4*)(w + k);
                float4 xq = *(const float4*)(x + k);
                acc += wq.x * xq.x + wq.y * xq.y + wq.z * xq.z + wq.w * xq.w;
            }
            gi[g] = acc;
            const float* w2 = w_hh + (size_t)(g * 384 + u) * 384 + ks * 24;
            const float* h2 = hv + ks * 24;
            float acc2 = 0.0f;
#pragma unroll
            for (int k = 0; k < 24; k += 4) {
                float4 wq = *(const float4*)(w2 + k);
                float4 hq = *(const float4*)(h2 + k);
                acc2 += wq.x * hq.x + wq.y * hq.y + wq.z * hq.z + wq.w * hq.w;
            }
            gh[g] = acc2;
        }
#pragma unroll
        for (int g = 0; g < 3; g++) {
            gi[g] += __shfl_xor_sync(0xFFFFFFFF, gi[g], 1);
            gi[g] += __shfl_xor_sync(0xFFFFFFFF, gi[g], 2);
            gi[g] += __shfl_xor_sync(0xFFFFFFFF, gi[g], 4);
            gi[g] += __shfl_xor_sync(0xFFFFFFFF, gi[g], 8);
            gh[g] += __shfl_xor_sync(0xFFFFFFFF, gh[g], 1);
            gh[g] += __shfl_xor_sync(0xFFFFFFFF, gh[g], 2);
            gh[g] += __shfl_xor_sync(0xFFFFFFFF, gh[g], 4);
            gh[g] += __shfl_xor_sync(0xFFFFFFFF, gh[g], 8);
        }
        if (ks == 0) {
            float i0 = gi[0] + b_ih[u],        h0v = gh[0] + b_hh[u];
            float i1 = gi[1] + b_ih[384 + u],  h1v = gh[1] + b_hh[384 + u];
            float i2 = gi[2] + b_ih[768 + u],  h2v = gh[2] + b_hh[768 + u];
            float r = 1.0f / (1.0f + expf(-(i0 + h0v)));
            float z = 1.0f / (1.0f + expf(-(i1 + h1v)));
            float n = tanhf(i2 + r * h2v);
            float hp = hv[u];
            g_cls_emb[b * HH + dir * 384 + u] = (1.0f - z) * n + z * hp;
        }
        return;
    }
    if (bid < GRUB3 + ROPEB) {
        int idx = (bid - GRUB3) * 256 + tid;
        int s = idx >> 5, t = idx & 31;
        float invf = powf(10000.0f, -2.0f * (float)t / 64.0f);
        float sn, cs;
        sincosf((float)s * invf, &sn, &cs);
        g_rope[idx] = make_float2(cs, sn);
        return;
    }
    if (bid < GRUB3 + ROPEB + SKIPB) {
        // ---- causal-skip tiles, 32-row band per block ----
        const int MTs[6] = {1, 2, 2, 3, 3, 3};
        const int NTs[6] = {0, 0, 1, 0, 1, 2};
        int idx = bid - (GRUB3 + ROPEB);
        int ti   = idx % 6;
        int band = (idx / 6) & 3;
        int be   = idx / 24;
        int b = be / ENT, e = be % ENT;
        int m0 = MTs[ti] * 128 + band * 32, n0 = NTs[ti] * 128;
        size_t rowbase = ((size_t)(b * ENT + e)) * SS;
        int cg = (tid & 31) * 4;
        float p0 = mask[b * SS + n0 + cg];
        float p1 = mask[b * SS + n0 + cg + 1];
        float p2 = mask[b * SS + n0 + cg + 2];
        float p3 = mask[b * SS + n0 + cg + 3];
        float4 v = make_float4(((p0 - 1.0f) * BIGF - BIGF) * 0.125f,
                               ((p1 - 1.0f) * BIGF - BIGF) * 0.125f,
                               ((p2 - 1.0f) * BIGF - BIGF) * 0.125f,
                               ((p3 - 1.0f) * BIGF - BIGF) * 0.125f);
#pragma unroll
        for (int r = tid >> 5; r < 32; r += 8)
            __stcs((float4*)(out + (rowbase + m0 + r) * SS + n0 + cg), v);
        return;
    }
    if (bid < GRUB3 + ROPEB + SKIPB + CONVB2) {
        // ---- W1 fp32 -> fp8 (x32), 4 float4 per thread (MLP=4) ----
        int base = (bid - (GRUB3 + ROPEB + SKIPB)) * 1024 + tid;
        float4 v[4];
#pragma unroll
        for (int j = 0; j < 4; j++) {
            int i = base + j * 256;
            v[j] = *(const float4*)(dw + (size_t)(i / 192) * KDIM + (i % 192) * 4);
        }
#pragma unroll
        for (int j = 0; j < 4; j++) {
            int i = base + j * 256;
            int n = i / 192, kq = (i % 192) * 4;
            uint32_t w = fp8x4(v[j].x * WSCALE, v[j].y * WSCALE,
                               v[j].z * WSCALE, v[j].w * WSCALE);
            int e = n >> 7, row = n & 127, ch = kq >> 7, kc = kq & 127;
            size_t off = (size_t)(e * 6 + ch) * BLKB + dswz(row, kc & 0x70) + (kc & 15);
            *(uint32_t*)(g_wbf_blk + off) = w;
        }
        return;
    }
    {
        // ---- lhs fp32 -> fp8, 4 float4 per thread (MLP=4) ----
        size_t base = ((size_t)(bid - (GRUB3 + ROPEB + SKIPB + CONVB2)) * 1024 + tid) * 4;
        float4 v[4];
#pragma unroll
        for (int j = 0; j < 4; j++)
            v[j] = *(const float4*)(lhs + base + (size_t)j * 1024);
#pragma unroll
        for (int j = 0; j < 4; j++) {
            size_t i = base + (size_t)j * 1024;
            uint32_t w = fp8x4(v[j].x, v[j].y, v[j].z, v[j].w);
            int m = (int)(i / HH), k = (int)(i % HH);
            int mt = m >> 7, row = m & 127, ch = k >> 7, kc = k & 127;
            size_t off = (size_t)(mt * 6 + ch) * BLKB + dswz(row, kc & 0x70) + (kc & 15);
            *(uint32_t*)(g_hidden_blk + off) = w;
        }
    }
}

// ---------------------------------------------------------------------------
// Kernel 1b: extended bias, 4-way K-split. (validated — unchanged)
// ---------------------------------------------------------------------------
__global__ __launch_bounds__(256) void clsw_kernel(const float* __restrict__ dw,
                                                   const float* __restrict__ db)
{
    __shared__ float cl[BB][HH + 4];
    __shared__ float red[4][64][BB];
    for (int i = threadIdx.x; i < BB * HH; i += 256)
        cl[i / HH][i % HH] = g_cls_emb[i];
    __syncthreads();

    const int nl = threadIdx.x & 63;
    const int ks = threadIdx.x >> 6;
    const int n  = blockIdx.x * 64 + nl;
    const int k0 = ks * 192;

    const float* w = dw + (size_t)n * KDIM + HH + k0;
    float acc[BB];
#pragma unroll
    for (int b = 0; b < BB; b++) acc[b] = 0.0f;
#pragma unroll 4
    for (int k = 0; k < 192; k += 4) {
        float4 wv = *(const float4*)(w + k);
#pragma unroll
        for (int b = 0; b < BB; b++)
            acc[b] += wv.x * cl[b][k0 + k] + wv.y * cl[b][k0 + k + 1]
                    + wv.z * cl[b][k0 + k + 2] + wv.w * cl[b][k0 + k + 3];
    }
#pragma unroll
    for (int b = 0; b < BB; b++) red[ks][nl][b] = acc[b];
    __syncthreads();
    if (ks == 0) {
        float bias = db[n];
#pragma unroll
        for (int b = 0; b < BB; b++)
            g_clsw[b * NOUT + n] = red[0][nl][b] + red[1][nl][b] + red[2][nl][b]
                                 + red[3][nl][b] + bias;
    }
}

// ---------------------------------------------------------------------------
// Kernel 2 (FUSED, 512 threads = 16 warps, 4Mx4N, warp tile 32x32):
// one CTA per (e, b). 3-stage TMA ring, dense fp8 GEMM -> bias+RoPE ->
// bf16 q/k in SMEM -> 10 upper-tri logits tiles sequentially from SMEM.
// (byte-for-byte R13, validated)
// ---------------------------------------------------------------------------
#define NST2 3
#define QK_SMEM (8 * BLKB)                         /* 131072 */
#define DSMEM_FUSED (QK_SMEM + NST2 * 2 * BLKB)    /* 229376 */

__global__ __launch_bounds__(512) void fused_kernel(const float* __restrict__ mask,
                                                    float* __restrict__ out)
{
    extern __shared__ char fsm[];
    const uint32_t sQK   = smem_u32(fsm);
    const uint32_t sStg  = sQK + QK_SMEM;
    __shared__ uint64_t mbv[NST2];
    __shared__ float bias_s[128];
    const uint32_t mb0 = smem_u32(mbv);

    const int e = blockIdx.x;
    const int b = blockIdx.y;
    const int tid = threadIdx.x;
    const int lane = tid & 31;
    const int wid  = tid >> 5;          // 0..15
    const int warpM = wid >> 2;         // 0..3 (32-row strips)
    const int warpN = wid & 3;          // 0..3 (32-col strips)
    const int g = lane >> 2, q = lane & 3;
    const size_t rowbase = ((size_t)(b * ENT + e)) * SS;

    if (tid < 128) bias_s[tid] = g_clsw[b * NOUT + e * 128 + tid];
    if (tid == 0) {
#pragma unroll
        for (int s = 0; s < NST2; s++) mbar_init(mb0 + s * 8, 1);
    }
    __syncthreads();

    auto issue = [&](int k, int st) {
        int mt = k / 6, ch = k % 6;
        mbar_expect(mb0 + st * 8, 2 * BLKB);
        bulk_cp(sStg + st * 2 * BLKB,
                g_hidden_blk + ((size_t)(b * 4 + mt) * 6 + ch) * BLKB, BLKB, mb0 + st * 8);
        bulk_cp(sStg + st * 2 * BLKB + BLKB,
                g_wbf_blk + ((size_t)e * 6 + ch) * BLKB, BLKB, mb0 + st * 8);
    };
    if (tid == 0) { issue(0, 0); issue(1, 1); issue(2, 2); }

    float acc[2][4][4];
#pragma unroll
    for (int i = 0; i < 2; i++)
#pragma unroll
        for (int j = 0; j < 4; j++)
#pragma unroll
            for (int r = 0; r < 4; r++) acc[i][j][r] = 0.0f;

    // ---- dense phase: 24 chunks, 3-stage ring ------------------------------
    for (int k = 0; k < 24; k++) {
        const int st = k % NST2;
        mbar_wait(mb0 + st * 8, (uint32_t)((k / NST2) & 1));

        const uint32_t aS = sStg + st * 2 * BLKB;
        const uint32_t bS = aS + BLKB;
#pragma unroll
        for (int kstep = 0; kstep < 4; kstep++) {
            const int colb = kstep * 32 + (lane >> 4) * 16;
            uint32_t areg[2][4], breg[4][2];
#pragma unroll
            for (int mi = 0; mi < 2; mi++)
                ldsm4(areg[mi], aS + dswz(warpM * 32 + mi * 16 + (lane & 15), colb));
#pragma unroll
            for (int jp = 0; jp < 2; jp++) {
                uint32_t t4[4];
                ldsm4(t4, bS + dswz(warpN * 32 + jp * 16 + (lane & 15), colb));
                breg[jp * 2][0]     = t4[0];
                breg[jp * 2 + 1][0] = t4[1];
                breg[jp * 2][1]     = t4[2];
                breg[jp * 2 + 1][1] = t4[3];
            }
#pragma unroll
            for (int mi = 0; mi < 2; mi++)
#pragma unroll
                for (int j = 0; j < 4; j++)
                    mma16832f8(acc[mi][j], areg[mi], breg[j]);
        }

        if ((k % 6) == 5) {
            // ---- m-tile epilogue: unscale + bias + RoPE -> bf16 SMEM qk ----
            const int mt = k / 6;
#pragma unroll
            for (int mi = 0; mi < 2; mi++) {
#pragma unroll
                for (int h = 0; h < 2; h++) {
                    int row = warpM * 32 + mi * 16 + h * 8 + g;
                    int s = mt * 128 + row;
#pragma unroll
                    for (int j = 0; j < 4; j++) {
                        int c = warpN * 32 + j * 8 + 2 * q;
                        float x = acc[mi][j][h * 2]     * WISCALE + bias_s[c];
                        float y = acc[mi][j][h * 2 + 1] * WISCALE + bias_s[c + 1];
                        int t = (c & 63) >> 1;
                        float2 rc = g_rope[s * 32 + t];
                        float rx = x * rc.x - y * rc.y;
                        float ry = y * rc.x + x * rc.y;
                        __nv_bfloat162 p = __floats2bfloat162_rn(rx, ry);
                        int qk = c >> 6, col = c & 63;
                        uint32_t off = (uint32_t)(qk * 4 + mt) * BLKB
                                     + dswz(row, (col >> 3) << 4) + (col & 7) * 2;
                        *(uint32_t*)(fsm + off) = *(uint32_t*)&p;
                        acc[mi][j][h * 2] = 0.0f;
                        acc[mi][j][h * 2 + 1] = 0.0f;
                    }
                }
            }
        }

        __syncthreads();               // stage consumed (+ epi visible)
        if (tid == 0 && k + NST2 < 24) issue(k + NST2, st);
    }

    // ---- logits phase: 10 upper-tri tiles from SMEM ------------------------
    const int MTs[10] = {0, 0, 0, 0, 1, 1, 1, 2, 2, 3};
    const int NTs[10] = {0, 1, 2, 3, 1, 2, 3, 2, 3, 3};

    for (int ti = 0; ti < 10; ti++) {
        const int mt = MTs[ti], nt = NTs[ti];
        const int m0 = mt * 128, n0 = nt * 128;
        const uint32_t sQ = sQK + (uint32_t)mt * BLKB;
        const uint32_t sK = sQK + (uint32_t)(4 + nt) * BLKB;

        float lac[2][4][4];
#pragma unroll
        for (int i = 0; i < 2; i++)
#pragma unroll
            for (int j = 0; j < 4; j++)
#pragma unroll
                for (int r = 0; r < 4; r++) lac[i][j][r] = 0.0f;

#pragma unroll
        for (int kstep = 0; kstep < 4; kstep++) {
            const int colb = kstep * 32 + (lane >> 4) * 16;
            uint32_t areg[2][4], breg[4][2];
#pragma unroll
            for (int mi = 0; mi < 2; mi++)
                ldsm4(areg[mi], sQ + dswz(warpM * 32 + mi * 16 + (lane & 15), colb));
#pragma unroll
            for (int jp = 0; jp < 2; jp++) {
                uint32_t t4[4];
                ldsm4(t4, sK + dswz(warpN * 32 + jp * 16 + (lane & 15), colb));
                breg[jp * 2][0]     = t4[0];
                breg[jp * 2 + 1][0] = t4[1];
                breg[jp * 2][1]     = t4[2];
                breg[jp * 2 + 1][1] = t4[3];
            }
#pragma unroll
            for (int mi = 0; mi < 2; mi++)
#pragma unroll
                for (int j = 0; j < 4; j++)
                    mma16816(lac[mi][j], areg[mi], breg[j]);
        }

        const int nbase = n0 + warpN * 32;
        float p0[4], p1[4];
#pragma unroll
        for (int j = 0; j < 4; j++) {
            int c = nbase + j * 8 + 2 * q;
            p0[j] = mask[b * SS + c];
            p1[j] = mask[b * SS + c + 1];
        }

#pragma unroll
        for (int mi = 0; mi < 2; mi++) {
#pragma unroll
            for (int h = 0; h < 2; h++) {
                int m = m0 + warpM * 32 + mi * 16 + h * 8 + g;
                size_t orow = (rowbase + m) * SS;
#pragma unroll
                for (int j = 0; j < 4; j++) {
                    int c = nbase + j * 8 + 2 * q;
                    float x = lac[mi][j][h * 2];
                    float y = lac[mi][j][h * 2 + 1];
                    x = x * p0[j] - (1.0f - p0[j]) * BIGF;
                    y = y * p1[j] - (1.0f - p1[j]) * BIGF;
                    if (m > c)     x -= BIGF;
                    if (m > c + 1) y -= BIGF;
                    __stcs((float2*)(out + orow + c), make_float2(x * 0.125f, y * 0.125f));
                }
            }
        }
    }
}

// ---------------------------------------------------------------------------
extern "C" void kernel_launch(void* const* d_in, const int* in_sizes, int n_in,
                              void* d_out, int out_size)
{
    const float* lhs    = (const float*)d_in[0];
    const float* cls    = (const float*)d_in[1];
    const float* h0     = (const float*)d_in[2];
    const float* mask   = (const float*)d_in[3];
    const float* w_ih_f = (const float*)d_in[4];
    const float* w_hh_f = (const float*)d_in[5];
    const float* b_ih_f = (const float*)d_in[6];
    const float* b_hh_f = (const float*)d_in[7];
    const float* w_ih_b = (const float*)d_in[8];
    const float* w_hh_b = (const float*)d_in[9];
    const float* b_ih_b = (const float*)d_in[10];
    const float* b_hh_b = (const float*)d_in[11];
    const float* dw     = (const float*)d_in[12];
    const float* db     = (const float*)d_in[13];
    float* out = (float*)d_out;

    cudaFuncSetAttribute(fused_kernel, cudaFuncAttributeMaxDynamicSharedMemorySize,
                         DSMEM_FUSED);

    prep_kernel<<<PREPB, 256>>>(dw, lhs, cls, h0, w_ih_f, w_hh_f, b_ih_f, b_hh_f,
                                w_ih_b, w_hh_b, b_ih_b, b_hh_b, mask, out);
    clsw_kernel<<<NOUT / 64, 256>>>(dw, db);

    fused_kernel<<<dim3(ENT, BB), 512, DSMEM_FUSED>>>(mask, out);
}